// round 6
// baseline (speedup 1.0000x reference)
#include <cuda_runtime.h>

// EthanolSNN: 3-layer LIF SNN inference. T=256, B=8192, D=64, H1=28, H2=14.
// Output mem3 [T, B, 1] fp32.
//
// Numerical-matching design (vs JAX/XLA:GPU + cuBLAS reference):
//  - every dot product is a SINGLE serial ascending-index FMA chain (cuBLAS order)
//  - bias added as a separate rounded add after the chain
//  - LIF update uses separate mul.rn / add.rn (no contraction): RN(RN(RN(b*m)+cur)-reset)
//  - reset subtract is a single exact-operand rounding (reset in {0,1})
//  - threshold compares m>1  ==  (m-1)>0 in fp32 (Sterbenz)
//
// Parallelization: 2 threads per element, split by NEURON halves (not k), so
// accumulation order per neuron is untouched. f32x2 packs two neurons per op
// (per-lane exact fp32). Spikes exchanged across the pair via shuffle.

typedef unsigned long long ull_t;

#define TT 256
#define BB 8192
#define DD 64
#define HH1 28
#define HH2 14

__device__ __forceinline__ ull_t pk2(float lo, float hi) {
    ull_t r;
    asm("mov.b64 %0, {%1, %2};" : "=l"(r) : "f"(lo), "f"(hi));
    return r;
}
__device__ __forceinline__ void upk2(ull_t v, float& lo, float& hi) {
    asm("mov.b64 {%0, %1}, %2;" : "=f"(lo), "=f"(hi) : "l"(v));
}
__device__ __forceinline__ ull_t fma2(ull_t a, ull_t b, ull_t c) {
    ull_t d;
    asm("fma.rn.f32x2 %0, %1, %2, %3;" : "=l"(d) : "l"(a), "l"(b), "l"(c));
    return d;
}
__device__ __forceinline__ ull_t add2(ull_t a, ull_t b) {
    ull_t d;
    asm("add.rn.f32x2 %0, %1, %2;" : "=l"(d) : "l"(a), "l"(b));
    return d;
}
__device__ __forceinline__ ull_t mul2(ull_t a, ull_t b) {
    ull_t d;
    asm("mul.rn.f32x2 %0, %1, %2;" : "=l"(d) : "l"(a), "l"(b));
    return d;
}

__global__ void __launch_bounds__(64, 1)
snn_fused_kernel(const float* __restrict__ x,
                 const float* __restrict__ W1, const float* __restrict__ b1,
                 const float* __restrict__ W2, const float* __restrict__ b2,
                 const float* __restrict__ W3, const float* __restrict__ b3,
                 float* __restrict__ out)
{
    // w1p[k][qq*8+j] = {W1[qq*14+2j][k], W1[qq*14+2j+1][k]}  (row stride 16 ull = 128B)
    // w2p[i][qq*4+m] = {W2[7qq+2m][i],   W2[7qq+2m+1][i]}    (row stride 8 ull = 64B; m=3 hi lane padded 0)
    __shared__ __align__(16) ull_t w1p[DD * 16];
    __shared__ __align__(16) ull_t w2p[HH1 * 8];
    __shared__ ull_t b1p[14];     // [qq*7+i] = {b1[qq*14+2i], b1[qq*14+2i+1]}
    __shared__ ull_t b2p[8];      // [qq*4+m]
    __shared__ float w3s[14];
    __shared__ float b3s;

    const int tid  = threadIdx.x;
    const int lane = tid & 31;
    const int warp = tid >> 5;
    const int p    = lane >> 1;            // element slot within warp (0..15)
    const int q    = lane & 1;             // neuron-half owner
    const int e    = blockIdx.x * 32 + warp * 16 + p;

    // ---- pack weights into shared ----
    for (int idx = tid; idx < DD * 16; idx += 64) {
        int k = idx >> 4, r = idx & 15, qq = r >> 3, j = r & 7;
        float lo = 0.f, hi = 0.f;
        if (j < 7) {
            lo = W1[(qq * 14 + 2 * j)     * DD + k];
            hi = W1[(qq * 14 + 2 * j + 1) * DD + k];
        }
        w1p[idx] = pk2(lo, hi);
    }
    for (int idx = tid; idx < HH1 * 8; idx += 64) {
        int i = idx >> 3, r = idx & 7, qq = r >> 2, m = r & 3;
        float lo = (2 * m     < 7) ? W2[(qq * 7 + 2 * m)     * HH1 + i] : 0.f;
        float hi = (2 * m + 1 < 7) ? W2[(qq * 7 + 2 * m + 1) * HH1 + i] : 0.f;
        w2p[idx] = pk2(lo, hi);
    }
    if (tid < 14) {
        int qq = tid / 7, ii = tid - qq * 7;
        b1p[tid] = pk2(b1[qq * 14 + 2 * ii], b1[qq * 14 + 2 * ii + 1]);
        w3s[tid] = W3[tid];
    }
    if (tid < 8) {
        int qq = tid >> 2, m = tid & 3;
        float lo = (2 * m     < 7) ? b2[qq * 7 + 2 * m]     : 0.f;
        float hi = (2 * m + 1 < 7) ? b2[qq * 7 + 2 * m + 1] : 0.f;
        b2p[tid] = pk2(lo, hi);
    }
    if (tid == 0) b3s = b3[0];
    __syncthreads();

    const ull_t* w1q = w1p + q * 8;    // this thread's neuron-half weight columns
    const ull_t* w2q = w2p + q * 4;

    ull_t b1own[7], b2own[4];
    #pragma unroll
    for (int i = 0; i < 7; i++) b1own[i] = b1p[q * 7 + i];
    #pragma unroll
    for (int m = 0; m < 4; m++) b2own[m] = b2p[q * 4 + m];

    const ull_t BETA2 = pk2(0.9f, 0.9f);
    const ull_t NEG2  = pk2(-1.0f, -1.0f);

    ull_t m1v[7], m2v[4];
    #pragma unroll
    for (int i = 0; i < 7; i++) m1v[i] = 0ULL;
    #pragma unroll
    for (int m = 0; m < 4; m++) m2v[m] = 0ULL;
    float m3 = 0.0f;

    const float*  xbase = x + (size_t)e * DD;
    const size_t  xstep = (size_t)BB * DD;

    #pragma unroll 1
    for (int t = 0; t < TT; t++) {
        // ---- load x_t (this element's full 64 inputs; pair reads coalesce/dedup) ----
        const float4* xp = (const float4*)(xbase + (size_t)t * xstep);
        float4 xr[16];
        #pragma unroll
        for (int i = 0; i < 16; i++) xr[i] = xp[i];

        // ---- prefetch next timestep's x into L2 (no register cost) ----
        if (t + 1 < TT) {
            const char* pf = (const char*)(xbase + (size_t)(t + 1) * xstep) + q * 128;
            asm volatile("prefetch.global.L2 [%0];" :: "l"(pf));
        }

        // ================ layer 1: serial ascending-k FMA chain, 14 owned neurons ======
        ull_t acc[7];
        #pragma unroll
        for (int j = 0; j < 7; j++) acc[j] = 0ULL;

        #pragma unroll
        for (int i8 = 0; i8 < 16; i8++) {
            float xv[4] = {xr[i8].x, xr[i8].y, xr[i8].z, xr[i8].w};
            #pragma unroll
            for (int c = 0; c < 4; c++) {
                const int k = i8 * 4 + c;
                ull_t xx = pk2(xv[c], xv[c]);
                const ulonglong2* wr = (const ulonglong2*)(w1q + (size_t)k * 16);
                ulonglong2 wa = wr[0], wb = wr[1], wc = wr[2];
                ull_t w7 = (w1q + (size_t)k * 16)[6];
                acc[0] = fma2(xx, wa.x, acc[0]);
                acc[1] = fma2(xx, wa.y, acc[1]);
                acc[2] = fma2(xx, wb.x, acc[2]);
                acc[3] = fma2(xx, wb.y, acc[3]);
                acc[4] = fma2(xx, wc.x, acc[4]);
                acc[5] = fma2(xx, wc.y, acc[5]);
                acc[6] = fma2(xx, w7,   acc[6]);
            }
        }

        // ================ LIF layer 1 (exact XLA rounding sequence) =====================
        float s1own[14];
        #pragma unroll
        for (int i = 0; i < 7; i++) {
            ull_t mold = m1v[i];
            float mlo, mhi;
            upk2(mold, mlo, mhi);
            float rlo = (mlo > 1.0f) ? 1.0f : 0.0f;
            float rhi = (mhi > 1.0f) ? 1.0f : 0.0f;
            ull_t cur = add2(acc[i], b1own[i]);           // dot + bias (separate round)
            ull_t mb  = mul2(BETA2, mold);                // RN(b*m)
            ull_t tmp = add2(mb, cur);                    // RN(.. + cur)
            ull_t mn  = fma2(pk2(rlo, rhi), NEG2, tmp);   // RN(.. - reset), exact product
            m1v[i] = mn;
            float nlo, nhi;
            upk2(mn, nlo, nhi);
            s1own[2 * i]     = (nlo > 1.0f) ? 1.0f : 0.0f;
            s1own[2 * i + 1] = (nhi > 1.0f) ? 1.0f : 0.0f;
        }

        // ---- exchange spike halves across the pair ----
        float s1o[14];
        #pragma unroll
        for (int i = 0; i < 7; i++) {
            ull_t sp = pk2(s1own[2 * i], s1own[2 * i + 1]);
            ull_t g  = __shfl_xor_sync(0xFFFFFFFFu, sp, 1);
            upk2(g, s1o[2 * i], s1o[2 * i + 1]);
        }
        float s1all[28];
        #pragma unroll
        for (int i = 0; i < 14; i++) {
            s1all[i]      = q ? s1o[i]   : s1own[i];
            s1all[14 + i] = q ? s1own[i] : s1o[i];
        }

        // ================ layer 2: serial ascending-i FMA chain, 7 owned h2 neurons ====
        ull_t a2[4];
        #pragma unroll
        for (int m = 0; m < 4; m++) a2[m] = 0ULL;
        #pragma unroll
        for (int i = 0; i < HH1; i++) {
            ull_t ss = pk2(s1all[i], s1all[i]);
            const ulonglong2* wr = (const ulonglong2*)(w2q + (size_t)i * 8);
            ulonglong2 u0 = wr[0], u1 = wr[1];
            a2[0] = fma2(ss, u0.x, a2[0]);
            a2[1] = fma2(ss, u0.y, a2[1]);
            a2[2] = fma2(ss, u1.x, a2[2]);
            a2[3] = fma2(ss, u1.y, a2[3]);
        }

        // ================ LIF layer 2 ==================================================
        float s2own[8];
        #pragma unroll
        for (int m = 0; m < 4; m++) {
            ull_t mold = m2v[m];
            float mlo, mhi;
            upk2(mold, mlo, mhi);
            float rlo = (mlo > 1.0f) ? 1.0f : 0.0f;
            float rhi = (mhi > 1.0f) ? 1.0f : 0.0f;
            ull_t cur = add2(a2[m], b2own[m]);
            ull_t mb  = mul2(BETA2, mold);
            ull_t tmp = add2(mb, cur);
            ull_t mn  = fma2(pk2(rlo, rhi), NEG2, tmp);
            m2v[m] = mn;
            float nlo, nhi;
            upk2(mn, nlo, nhi);
            s2own[2 * m]     = (nlo > 1.0f) ? 1.0f : 0.0f;
            s2own[2 * m + 1] = (nhi > 1.0f) ? 1.0f : 0.0f;
        }

        // ---- exchange s2 halves ----
        float s2o[8];
        #pragma unroll
        for (int m = 0; m < 4; m++) {
            ull_t sp = pk2(s2own[2 * m], s2own[2 * m + 1]);
            ull_t g  = __shfl_xor_sync(0xFFFFFFFFu, sp, 1);
            upk2(g, s2o[2 * m], s2o[2 * m + 1]);
        }
        float s2all[14];
        #pragma unroll
        for (int i = 0; i < 7; i++) {
            s2all[i]     = q ? s2o[i]   : s2own[i];
            s2all[7 + i] = q ? s2own[i] : s2o[i];
        }

        // ================ layer 3 + LIF 3 (serial FMA chain, then separate rounds) =====
        float c3 = 0.0f;
        #pragma unroll
        for (int i = 0; i < HH2; i++) c3 = fmaf(s2all[i], w3s[i], c3);
        float cur3 = __fadd_rn(c3, b3s);

        float r3  = (m3 > 1.0f) ? 1.0f : 0.0f;
        float mb3 = __fmul_rn(0.9f, m3);
        float t3  = __fadd_rn(mb3, cur3);
        m3 = __fsub_rn(t3, r3);

        if (q == 0) out[(size_t)t * BB + e] = m3;
    }
}

extern "C" void kernel_launch(void* const* d_in, const int* in_sizes, int n_in,
                              void* d_out, int out_size) {
    const float* x  = (const float*)d_in[0];
    const float* W1 = (const float*)d_in[1];
    const float* b1 = (const float*)d_in[2];
    const float* W2 = (const float*)d_in[3];
    const float* b2 = (const float*)d_in[4];
    const float* W3 = (const float*)d_in[5];
    const float* b3 = (const float*)d_in[6];
    float* out = (float*)d_out;

    // 8192 elements, 32 per block (64 threads = 2 threads per element)
    snn_fused_kernel<<<256, 64>>>(x, W1, b1, W2, b2, W3, b3, out);
}